// round 5
// baseline (speedup 1.0000x reference)
#include <cuda_runtime.h>

#define Nn 50000
#define Ee 800000
#define INF 128
#define HH  128
#define OUTF 64

// ---- device scratch (static globals; no allocation) ----
__device__ __align__(16) float g_h1[Nn * HH];    // (x @ W1) * dinv[row]
__device__ __align__(16) float g_h [Nn * HH];    // relu(conv1) output
__device__ __align__(16) float g_m2[Nn * OUTF];  // (h @ Wmu) * dinv[row]
__device__ int   g_deg [Nn];
__device__ int   g_ptr [Nn + 1];
__device__ int   g_fill[Nn];
__device__ int   g_src [Ee];       // CSR-by-dst neighbor lists
__device__ float g_dinv[Nn];
__device__ int   g_is64;           // 1 if edge_index is int64, 0 if int32

// ---------------- dtype detection ----------------
// int64 data: sampled values all in [0, Nn). int32 data read as int64 packs two
// random indices per word -> value has a nonzero high word with overwhelming
// probability; P(128 samples all look valid) ~ (1/Nn)^128 ~ 0.
__global__ void k_detect(const void* ei) {
    if (threadIdx.x == 0) {
        const long long* p = (const long long*)ei;
        int ok = 1;
        for (int i = 0; i < 64; i++) {             // src row head
            long long v = p[i];
            if (v < 0 || v >= Nn) { ok = 0; break; }
        }
        if (ok) {
            for (int i = 0; i < 64; i++) {         // dst row head
                long long v = p[Ee + i];
                if (v < 0 || v >= Nn) { ok = 0; break; }
            }
        }
        g_is64 = ok;
    }
}

__device__ __forceinline__ int edge_at(const void* ei, int which, int e, int is64) {
    // which: 0 = src row, 1 = dst row, layout [2, E]
    if (is64) return (int)((const long long*)ei)[(long)which * Ee + e];
    return ((const int*)ei)[(long)which * Ee + e];
}

// ---------------- CSR build ----------------
__global__ void k_zero() {
    int i = blockIdx.x * blockDim.x + threadIdx.x;
    if (i < Nn) { g_deg[i] = 0; g_fill[i] = 0; }
}

__global__ void k_deg(const void* __restrict__ ei) {
    int e = blockIdx.x * blockDim.x + threadIdx.x;
    if (e < Ee) {
        const int is64 = g_is64;
        int d = edge_at(ei, 1, e, is64);
        if (d >= 0 && d < Nn) atomicAdd(&g_deg[d], 1);
    }
}

// single-block exclusive scan of g_deg -> g_ptr, 1024 threads
__global__ void k_scan() {
    __shared__ int warp_sums[32];
    __shared__ int s_carry;
    int tid = threadIdx.x, lane = tid & 31, wid = tid >> 5;
    if (tid == 0) s_carry = 0;
    __syncthreads();
    for (int base = 0; base < Nn; base += 1024) {
        int i = base + tid;
        int v = (i < Nn) ? g_deg[i] : 0;
        int x = v;
        #pragma unroll
        for (int o = 1; o < 32; o <<= 1) {
            int t = __shfl_up_sync(0xffffffffu, x, o);
            if (lane >= o) x += t;
        }
        if (lane == 31) warp_sums[wid] = x;
        __syncthreads();
        if (wid == 0) {
            int s = warp_sums[lane];
            #pragma unroll
            for (int o = 1; o < 32; o <<= 1) {
                int t = __shfl_up_sync(0xffffffffu, s, o);
                if (lane >= o) s += t;
            }
            warp_sums[lane] = s;
        }
        __syncthreads();
        int incl = x + (wid > 0 ? warp_sums[wid - 1] : 0);
        int carry = s_carry;
        if (i < Nn) g_ptr[i] = carry + incl - v;   // exclusive prefix
        __syncthreads();
        if (tid == 1023) s_carry = carry + warp_sums[31];
        __syncthreads();
    }
    if (threadIdx.x == 0) g_ptr[Nn] = s_carry;
}

__global__ void k_dinv() {
    int i = blockIdx.x * blockDim.x + threadIdx.x;
    if (i < Nn) g_dinv[i] = rsqrtf((float)g_deg[i] + 1.0f);
}

__global__ void k_fill(const void* __restrict__ ei) {
    int e = blockIdx.x * blockDim.x + threadIdx.x;
    if (e < Ee) {
        const int is64 = g_is64;
        int d = edge_at(ei, 1, e, is64);
        int s = edge_at(ei, 0, e, is64);
        if (d >= 0 && d < Nn && s >= 0 && s < Nn) {
            int pos = g_ptr[d] + atomicAdd(&g_fill[d], 1);
            if (pos >= 0 && pos < Ee) g_src[pos] = s;
        }
    }
}

// ---- dense GEMM: Y[row,:] = (X[row,:128] @ W[128,OUTC]) * dscale[row] ----
// block = 256 threads, tile = 64 rows x OUTC cols, K-panels of 32
template <int OUTC>
__global__ void k_gemm(const float* __restrict__ X, const float* __restrict__ W,
                       const float* __restrict__ dscale,
                       float* __restrict__ Y, int nrows) {
    __shared__ float xs[64][33];          // padded to kill bank conflicts
    __shared__ float ws[32 * OUTC];
    constexpr int NH = OUTC / 64;          // 2 for 128, 1 for 64

    int tid  = threadIdx.x;
    int tx   = tid & 15;                   // col group
    int ty   = tid >> 4;                   // row group
    int row0 = blockIdx.x * 64;

    float acc[4][NH * 4];
    #pragma unroll
    for (int i = 0; i < 4; i++)
        #pragma unroll
        for (int j = 0; j < NH * 4; j++) acc[i][j] = 0.0f;

    int lr = tid >> 2;                     // 0..63 : row for x-tile load
    int lc = (tid & 3) * 8;                // 0,8,16,24 : k-offset for x-tile load

    for (int k0 = 0; k0 < 128; k0 += 32) {
        // load X tile (64 x 32)
        if (row0 + lr < nrows) {
            const float* xp = X + (long)(row0 + lr) * 128 + k0 + lc;
            float4 v0 = *(const float4*)(xp);
            float4 v1 = *(const float4*)(xp + 4);
            xs[lr][lc + 0] = v0.x; xs[lr][lc + 1] = v0.y; xs[lr][lc + 2] = v0.z; xs[lr][lc + 3] = v0.w;
            xs[lr][lc + 4] = v1.x; xs[lr][lc + 5] = v1.y; xs[lr][lc + 6] = v1.z; xs[lr][lc + 7] = v1.w;
        } else {
            #pragma unroll
            for (int j = 0; j < 8; j++) xs[lr][lc + j] = 0.0f;
        }
        // load W panel (32 x OUTC), flat copy
        {
            const float4* wp = (const float4*)(W + k0 * OUTC);
            float4* wsp = (float4*)ws;
            #pragma unroll
            for (int f = 0; f < (32 * OUTC / 4) / 256; f++)
                wsp[tid + f * 256] = wp[tid + f * 256];
        }
        __syncthreads();

        #pragma unroll
        for (int kk = 0; kk < 32; kk++) {
            float a0 = xs[ty * 4 + 0][kk];
            float a1 = xs[ty * 4 + 1][kk];
            float a2 = xs[ty * 4 + 2][kk];
            float a3 = xs[ty * 4 + 3][kk];
            #pragma unroll
            for (int h2 = 0; h2 < NH; h2++) {
                float4 w = *(const float4*)&ws[kk * OUTC + h2 * 64 + tx * 4];
                acc[0][h2*4+0] += a0 * w.x; acc[0][h2*4+1] += a0 * w.y;
                acc[0][h2*4+2] += a0 * w.z; acc[0][h2*4+3] += a0 * w.w;
                acc[1][h2*4+0] += a1 * w.x; acc[1][h2*4+1] += a1 * w.y;
                acc[1][h2*4+2] += a1 * w.z; acc[1][h2*4+3] += a1 * w.w;
                acc[2][h2*4+0] += a2 * w.x; acc[2][h2*4+1] += a2 * w.y;
                acc[2][h2*4+2] += a2 * w.z; acc[2][h2*4+3] += a2 * w.w;
                acc[3][h2*4+0] += a3 * w.x; acc[3][h2*4+1] += a3 * w.y;
                acc[3][h2*4+2] += a3 * w.z; acc[3][h2*4+3] += a3 * w.w;
            }
        }
        __syncthreads();
    }

    #pragma unroll
    for (int i = 0; i < 4; i++) {
        int row = row0 + ty * 4 + i;
        if (row < nrows) {
            float sc = dscale[row];
            #pragma unroll
            for (int h2 = 0; h2 < NH; h2++) {
                float4 v = make_float4(acc[i][h2*4+0] * sc, acc[i][h2*4+1] * sc,
                                       acc[i][h2*4+2] * sc, acc[i][h2*4+3] * sc);
                *(float4*)&Y[(long)row * OUTC + h2 * 64 + tx * 4] = v;
            }
        }
    }
}

// ---- aggregation layer 1: warp per dst node ----
// index loads: 1 coalesced LDG per 32 edges + shfl broadcast; row gathers 4-deep.
__global__ void k_agg1(const float* __restrict__ b1) {
    int warp = (blockIdx.x * blockDim.x + threadIdx.x) >> 5;
    int lane = threadIdx.x & 31;
    if (warp >= Nn) return;
    int node = warp;
    int beg = g_ptr[node], end = g_ptr[node + 1];
    float dd = g_dinv[node];
    const float4* __restrict__ H1 = (const float4*)g_h1;

    float4 acc = make_float4(0.f, 0.f, 0.f, 0.f);
    for (int e0 = beg; e0 < end; e0 += 32) {
        int n = end - e0; if (n > 32) n = 32;
        int myidx = (lane < n) ? g_src[e0 + lane] : 0;
        int j = 0;
        for (; j + 4 <= n; j += 4) {
            int s0 = __shfl_sync(0xffffffffu, myidx, j + 0);
            int s1 = __shfl_sync(0xffffffffu, myidx, j + 1);
            int s2 = __shfl_sync(0xffffffffu, myidx, j + 2);
            int s3 = __shfl_sync(0xffffffffu, myidx, j + 3);
            float4 v0 = H1[(long)s0 * 32 + lane];
            float4 v1 = H1[(long)s1 * 32 + lane];
            float4 v2 = H1[(long)s2 * 32 + lane];
            float4 v3 = H1[(long)s3 * 32 + lane];
            acc.x += v0.x + v1.x + v2.x + v3.x;
            acc.y += v0.y + v1.y + v2.y + v3.y;
            acc.z += v0.z + v1.z + v2.z + v3.z;
            acc.w += v0.w + v1.w + v2.w + v3.w;
        }
        for (; j < n; j++) {
            int s = __shfl_sync(0xffffffffu, myidx, j);
            float4 v = H1[(long)s * 32 + lane];
            acc.x += v.x; acc.y += v.y; acc.z += v.z; acc.w += v.w;
        }
    }
    float4 sf = H1[(long)node * 32 + lane];        // self term: already h1*dinv[node]
    float4 b  = ((const float4*)b1)[lane];
    float4 r;
    r.x = fmaxf((acc.x + sf.x) * dd + b.x, 0.f);
    r.y = fmaxf((acc.y + sf.y) * dd + b.y, 0.f);
    r.z = fmaxf((acc.z + sf.z) * dd + b.z, 0.f);
    r.w = fmaxf((acc.w + sf.w) * dd + b.w, 0.f);
    ((float4*)g_h)[(long)node * 32 + lane] = r;
}

// ---- aggregation layer 2 + fused epilogue (mu, logstd=mu, zeta) ----
__global__ void k_agg2(const float* __restrict__ bmu, const float* __restrict__ eps,
                       float* __restrict__ out) {
    int warp = (blockIdx.x * blockDim.x + threadIdx.x) >> 5;
    int lane = threadIdx.x & 31;
    if (warp >= Nn) return;
    int node = warp;
    int beg = g_ptr[node], end = g_ptr[node + 1];
    float dd = g_dinv[node];
    const float2* __restrict__ M = (const float2*)g_m2;

    float2 acc = make_float2(0.f, 0.f);
    for (int e0 = beg; e0 < end; e0 += 32) {
        int n = end - e0; if (n > 32) n = 32;
        int myidx = (lane < n) ? g_src[e0 + lane] : 0;
        int j = 0;
        for (; j + 4 <= n; j += 4) {
            int s0 = __shfl_sync(0xffffffffu, myidx, j + 0);
            int s1 = __shfl_sync(0xffffffffu, myidx, j + 1);
            int s2 = __shfl_sync(0xffffffffu, myidx, j + 2);
            int s3 = __shfl_sync(0xffffffffu, myidx, j + 3);
            float2 v0 = M[(long)s0 * 32 + lane];
            float2 v1 = M[(long)s1 * 32 + lane];
            float2 v2 = M[(long)s2 * 32 + lane];
            float2 v3 = M[(long)s3 * 32 + lane];
            acc.x += v0.x + v1.x + v2.x + v3.x;
            acc.y += v0.y + v1.y + v2.y + v3.y;
        }
        for (; j < n; j++) {
            int s = __shfl_sync(0xffffffffu, myidx, j);
            float2 v = M[(long)s * 32 + lane];
            acc.x += v.x; acc.y += v.y;
        }
    }
    float2 sf = M[(long)node * 32 + lane];
    float2 b  = ((const float2*)bmu)[lane];
    float2 mu;
    mu.x = (acc.x + sf.x) * dd + b.x;
    mu.y = (acc.y + sf.y) * dd + b.y;

    float2 ep = ((const float2*)eps)[(long)node * 32 + lane];
    float2 z;
    z.x = mu.x + ep.x * __expf(mu.x);
    z.y = mu.y + ep.y * __expf(mu.y);

    long idx = (long)node * 32 + lane;
    ((float2*)out)[idx] = mu;                                   // mu
    ((float2*)(out + (long)Nn * OUTF))[idx] = mu;               // logstd == mu
    ((float2*)(out + 2L * Nn * OUTF))[idx] = z;                 // zeta
}

extern "C" void kernel_launch(void* const* d_in, const int* in_sizes, int n_in,
                              void* d_out, int out_size) {
    const float* x   = (const float*)d_in[0];
    const void*  ei  = d_in[1];                 // int64 or int32, detected on device
    const float* W1  = (const float*)d_in[2];
    const float* b1  = (const float*)d_in[3];
    const float* Wmu = (const float*)d_in[4];
    const float* bmu = (const float*)d_in[5];
    // d_in[6]=Wls, d_in[7]=bls are dead (reference reuses Wmu/bmu for logstd)
    const float* eps = (const float*)d_in[8];
    float* out = (float*)d_out;

    float *h1p, *hp, *m2p, *dvp;
    cudaGetSymbolAddress((void**)&h1p, g_h1);
    cudaGetSymbolAddress((void**)&hp,  g_h);
    cudaGetSymbolAddress((void**)&m2p, g_m2);
    cudaGetSymbolAddress((void**)&dvp, g_dinv);

    const int TB = 256;
    k_detect<<<1, 32>>>(ei);
    k_zero<<<(Nn + TB - 1) / TB, TB>>>();
    k_deg <<<(Ee + TB - 1) / TB, TB>>>(ei);
    k_scan<<<1, 1024>>>();
    k_dinv<<<(Nn + TB - 1) / TB, TB>>>();
    k_fill<<<(Ee + TB - 1) / TB, TB>>>(ei);

    k_gemm<HH><<<(Nn + 63) / 64, 256>>>(x, W1, dvp, h1p, Nn);
    k_agg1<<<(Nn * 32 + TB - 1) / TB, TB>>>(b1);
    k_gemm<OUTF><<<(Nn + 63) / 64, 256>>>(hp, Wmu, dvp, m2p, Nn);
    k_agg2<<<(Nn * 32 + TB - 1) / TB, TB>>>(bmu, eps, out);
}

// round 7
// speedup vs baseline: 1.1810x; 1.1810x over previous
#include <cuda_runtime.h>

#define Nn 50000
#define Ee 800000
#define INF 128
#define HH  128
#define OUTF 64
#define SCAN_BLK 1024
#define SCAN_NB ((Nn + SCAN_BLK - 1) / SCAN_BLK)   // 49

// ---- device scratch (static globals; no allocation) ----
__device__ __align__(16) float g_h1[Nn * HH];    // (x @ W1) * dinv[row]
__device__ __align__(16) float g_h [Nn * HH];    // relu(conv1) output
__device__ __align__(16) float g_m2[Nn * OUTF];  // (h @ Wmu) * dinv[row]
__device__ int   g_deg [Nn];
__device__ int   g_ptr [Nn + 1];
__device__ int   g_fill[Nn];
__device__ int   g_src [Ee];       // CSR-by-dst neighbor lists
__device__ float g_dinv[Nn];
__device__ int   g_is64;           // 1 if edge_index is int64, 0 if int32
__device__ int   g_bsum[SCAN_NB];  // per-block degree sums
__device__ int   g_boff[SCAN_NB];  // exclusive prefix of block sums

// ---------------- dtype detection (one warp, parallel loads + vote) ----------------
// int64 data: sampled values all in [0, Nn). int32 read as int64 packs two random
// indices per word -> high word nonzero with overwhelming probability.
__global__ void k_detect(const void* ei) {
    int lane = threadIdx.x;
    const long long* p = (const long long*)ei;
    long long v1 = p[lane];            // src row head
    long long v2 = p[Ee + lane];       // dst row head
    bool ok = (v1 >= 0 && v1 < Nn) && (v2 >= 0 && v2 < Nn);
    unsigned all = __all_sync(0xffffffffu, ok);
    if (lane == 0) g_is64 = all ? 1 : 0;
}

__device__ __forceinline__ int edge_at(const void* ei, int which, int e, int is64) {
    // which: 0 = src row, 1 = dst row, layout [2, E]
    if (is64) return (int)((const long long*)ei)[(long)which * Ee + e];
    return ((const int*)ei)[(long)which * Ee + e];
}

// ---------------- CSR build ----------------
__global__ void k_zero() {
    int i = blockIdx.x * blockDim.x + threadIdx.x;
    if (i < Nn) { g_deg[i] = 0; g_fill[i] = 0; }
}

__global__ void k_deg(const void* __restrict__ ei) {
    int e = blockIdx.x * blockDim.x + threadIdx.x;
    if (e < Ee) {
        const int is64 = g_is64;
        int d = edge_at(ei, 1, e, is64);
        if (d >= 0 && d < Nn) atomicAdd(&g_deg[d], 1);
    }
}

// ---- 3-phase multi-block scan (dinv fused into phase A) ----
// Phase A: each block scans 1024 degrees -> block-local exclusive prefix + block sum
__global__ void k_scanA() {
    __shared__ int warp_sums[32];
    int tid = threadIdx.x, lane = tid & 31, wid = tid >> 5;
    int i = blockIdx.x * SCAN_BLK + tid;
    int v = (i < Nn) ? g_deg[i] : 0;
    if (i < Nn) g_dinv[i] = rsqrtf((float)v + 1.0f);   // fused dinv
    int x = v;
    #pragma unroll
    for (int o = 1; o < 32; o <<= 1) {
        int t = __shfl_up_sync(0xffffffffu, x, o);
        if (lane >= o) x += t;
    }
    if (lane == 31) warp_sums[wid] = x;
    __syncthreads();
    if (wid == 0) {
        int s = warp_sums[lane];
        #pragma unroll
        for (int o = 1; o < 32; o <<= 1) {
            int t = __shfl_up_sync(0xffffffffu, s, o);
            if (lane >= o) s += t;
        }
        warp_sums[lane] = s;
    }
    __syncthreads();
    int incl = x + (wid > 0 ? warp_sums[wid - 1] : 0);
    if (i < Nn) g_ptr[i] = incl - v;                 // block-local exclusive prefix
    if (tid == SCAN_BLK - 1) g_bsum[blockIdx.x] = incl;
}

// Phase B: one warp scans SCAN_NB block sums (exclusive)
__global__ void k_scanB() {
    int lane = threadIdx.x;
    int carry = 0;
    for (int base = 0; base < SCAN_NB; base += 32) {
        int idx = base + lane;
        int v = (idx < SCAN_NB) ? g_bsum[idx] : 0;
        int x = v;
        #pragma unroll
        for (int o = 1; o < 32; o <<= 1) {
            int t = __shfl_up_sync(0xffffffffu, x, o);
            if (lane >= o) x += t;
        }
        if (idx < SCAN_NB) g_boff[idx] = carry + x - v;
        carry += __shfl_sync(0xffffffffu, x, 31);
    }
    if (lane == 0) g_ptr[Nn] = Ee;                   // total degree == E (all dst valid)
}

// Phase C: add block offsets
__global__ void k_scanC() {
    int i = blockIdx.x * SCAN_BLK + threadIdx.x;
    if (i < Nn) g_ptr[i] += g_boff[blockIdx.x];
}

__global__ void k_fill(const void* __restrict__ ei) {
    int e = blockIdx.x * blockDim.x + threadIdx.x;
    if (e < Ee) {
        const int is64 = g_is64;
        int d = edge_at(ei, 1, e, is64);
        int s = edge_at(ei, 0, e, is64);
        if (d >= 0 && d < Nn && s >= 0 && s < Nn) {
            int pos = g_ptr[d] + atomicAdd(&g_fill[d], 1);
            if (pos >= 0 && pos < Ee) g_src[pos] = s;
        }
    }
}

// ---- dense GEMM: Y[row,:] = (X[row,:128] @ W[128,OUTC]) * dscale[row] ----
// block = 256 threads, tile = 64 rows x OUTC cols, K-panels of 32
template <int OUTC>
__global__ void k_gemm(const float* __restrict__ X, const float* __restrict__ W,
                       const float* __restrict__ dscale,
                       float* __restrict__ Y, int nrows) {
    __shared__ float xs[64][33];          // padded to kill bank conflicts
    __shared__ float ws[32 * OUTC];
    constexpr int NH = OUTC / 64;          // 2 for 128, 1 for 64

    int tid  = threadIdx.x;
    int tx   = tid & 15;                   // col group
    int ty   = tid >> 4;                   // row group
    int row0 = blockIdx.x * 64;

    float acc[4][NH * 4];
    #pragma unroll
    for (int i = 0; i < 4; i++)
        #pragma unroll
        for (int j = 0; j < NH * 4; j++) acc[i][j] = 0.0f;

    int lr = tid >> 2;                     // 0..63 : row for x-tile load
    int lc = (tid & 3) * 8;                // 0,8,16,24 : k-offset for x-tile load

    for (int k0 = 0; k0 < 128; k0 += 32) {
        // load X tile (64 x 32)
        if (row0 + lr < nrows) {
            const float* xp = X + (long)(row0 + lr) * 128 + k0 + lc;
            float4 v0 = *(const float4*)(xp);
            float4 v1 = *(const float4*)(xp + 4);
            xs[lr][lc + 0] = v0.x; xs[lr][lc + 1] = v0.y; xs[lr][lc + 2] = v0.z; xs[lr][lc + 3] = v0.w;
            xs[lr][lc + 4] = v1.x; xs[lr][lc + 5] = v1.y; xs[lr][lc + 6] = v1.z; xs[lr][lc + 7] = v1.w;
        } else {
            #pragma unroll
            for (int j = 0; j < 8; j++) xs[lr][lc + j] = 0.0f;
        }
        // load W panel (32 x OUTC), flat copy
        {
            const float4* wp = (const float4*)(W + k0 * OUTC);
            float4* wsp = (float4*)ws;
            #pragma unroll
            for (int f = 0; f < (32 * OUTC / 4) / 256; f++)
                wsp[tid + f * 256] = wp[tid + f * 256];
        }
        __syncthreads();

        #pragma unroll
        for (int kk = 0; kk < 32; kk++) {
            float a0 = xs[ty * 4 + 0][kk];
            float a1 = xs[ty * 4 + 1][kk];
            float a2 = xs[ty * 4 + 2][kk];
            float a3 = xs[ty * 4 + 3][kk];
            #pragma unroll
            for (int h2 = 0; h2 < NH; h2++) {
                float4 w = *(const float4*)&ws[kk * OUTC + h2 * 64 + tx * 4];
                acc[0][h2*4+0] += a0 * w.x; acc[0][h2*4+1] += a0 * w.y;
                acc[0][h2*4+2] += a0 * w.z; acc[0][h2*4+3] += a0 * w.w;
                acc[1][h2*4+0] += a1 * w.x; acc[1][h2*4+1] += a1 * w.y;
                acc[1][h2*4+2] += a1 * w.z; acc[1][h2*4+3] += a1 * w.w;
                acc[2][h2*4+0] += a2 * w.x; acc[2][h2*4+1] += a2 * w.y;
                acc[2][h2*4+2] += a2 * w.z; acc[2][h2*4+3] += a2 * w.w;
                acc[3][h2*4+0] += a3 * w.x; acc[3][h2*4+1] += a3 * w.y;
                acc[3][h2*4+2] += a3 * w.z; acc[3][h2*4+3] += a3 * w.w;
            }
        }
        __syncthreads();
    }

    #pragma unroll
    for (int i = 0; i < 4; i++) {
        int row = row0 + ty * 4 + i;
        if (row < nrows) {
            float sc = dscale[row];
            #pragma unroll
            for (int h2 = 0; h2 < NH; h2++) {
                float4 v = make_float4(acc[i][h2*4+0] * sc, acc[i][h2*4+1] * sc,
                                       acc[i][h2*4+2] * sc, acc[i][h2*4+3] * sc);
                *(float4*)&Y[(long)row * OUTC + h2 * 64 + tx * 4] = v;
            }
        }
    }
}

// ---- aggregation layer 1: warp per dst node ----
// index loads: 1 coalesced LDG per 32 edges + shfl broadcast; row gathers 4-deep.
__global__ void k_agg1(const float* __restrict__ b1) {
    int warp = (blockIdx.x * blockDim.x + threadIdx.x) >> 5;
    int lane = threadIdx.x & 31;
    if (warp >= Nn) return;
    int node = warp;
    int beg = g_ptr[node], end = g_ptr[node + 1];
    float dd = g_dinv[node];
    const float4* __restrict__ H1 = (const float4*)g_h1;

    float4 acc = make_float4(0.f, 0.f, 0.f, 0.f);
    for (int e0 = beg; e0 < end; e0 += 32) {
        int n = end - e0; if (n > 32) n = 32;
        int myidx = (lane < n) ? g_src[e0 + lane] : 0;
        int j = 0;
        for (; j + 4 <= n; j += 4) {
            int s0 = __shfl_sync(0xffffffffu, myidx, j + 0);
            int s1 = __shfl_sync(0xffffffffu, myidx, j + 1);
            int s2 = __shfl_sync(0xffffffffu, myidx, j + 2);
            int s3 = __shfl_sync(0xffffffffu, myidx, j + 3);
            float4 v0 = H1[(long)s0 * 32 + lane];
            float4 v1 = H1[(long)s1 * 32 + lane];
            float4 v2 = H1[(long)s2 * 32 + lane];
            float4 v3 = H1[(long)s3 * 32 + lane];
            acc.x += v0.x + v1.x + v2.x + v3.x;
            acc.y += v0.y + v1.y + v2.y + v3.y;
            acc.z += v0.z + v1.z + v2.z + v3.z;
            acc.w += v0.w + v1.w + v2.w + v3.w;
        }
        for (; j < n; j++) {
            int s = __shfl_sync(0xffffffffu, myidx, j);
            float4 v = H1[(long)s * 32 + lane];
            acc.x += v.x; acc.y += v.y; acc.z += v.z; acc.w += v.w;
        }
    }
    float4 sf = H1[(long)node * 32 + lane];        // self term: already h1*dinv[node]
    float4 b  = ((const float4*)b1)[lane];
    float4 r;
    r.x = fmaxf((acc.x + sf.x) * dd + b.x, 0.f);
    r.y = fmaxf((acc.y + sf.y) * dd + b.y, 0.f);
    r.z = fmaxf((acc.z + sf.z) * dd + b.z, 0.f);
    r.w = fmaxf((acc.w + sf.w) * dd + b.w, 0.f);
    ((float4*)g_h)[(long)node * 32 + lane] = r;
}

// ---- aggregation layer 2 + fused epilogue (mu, logstd=mu, zeta) ----
__global__ void k_agg2(const float* __restrict__ bmu, const float* __restrict__ eps,
                       float* __restrict__ out) {
    int warp = (blockIdx.x * blockDim.x + threadIdx.x) >> 5;
    int lane = threadIdx.x & 31;
    if (warp >= Nn) return;
    int node = warp;
    int beg = g_ptr[node], end = g_ptr[node + 1];
    float dd = g_dinv[node];
    const float2* __restrict__ M = (const float2*)g_m2;

    float2 acc = make_float2(0.f, 0.f);
    for (int e0 = beg; e0 < end; e0 += 32) {
        int n = end - e0; if (n > 32) n = 32;
        int myidx = (lane < n) ? g_src[e0 + lane] : 0;
        int j = 0;
        for (; j + 4 <= n; j += 4) {
            int s0 = __shfl_sync(0xffffffffu, myidx, j + 0);
            int s1 = __shfl_sync(0xffffffffu, myidx, j + 1);
            int s2 = __shfl_sync(0xffffffffu, myidx, j + 2);
            int s3 = __shfl_sync(0xffffffffu, myidx, j + 3);
            float2 v0 = M[(long)s0 * 32 + lane];
            float2 v1 = M[(long)s1 * 32 + lane];
            float2 v2 = M[(long)s2 * 32 + lane];
            float2 v3 = M[(long)s3 * 32 + lane];
            acc.x += v0.x + v1.x + v2.x + v3.x;
            acc.y += v0.y + v1.y + v2.y + v3.y;
        }
        for (; j < n; j++) {
            int s = __shfl_sync(0xffffffffu, myidx, j);
            float2 v = M[(long)s * 32 + lane];
            acc.x += v.x; acc.y += v.y;
        }
    }
    float2 sf = M[(long)node * 32 + lane];
    float2 b  = ((const float2*)bmu)[lane];
    float2 mu;
    mu.x = (acc.x + sf.x) * dd + b.x;
    mu.y = (acc.y + sf.y) * dd + b.y;

    float2 ep = ((const float2*)eps)[(long)node * 32 + lane];
    float2 z;
    z.x = mu.x + ep.x * __expf(mu.x);
    z.y = mu.y + ep.y * __expf(mu.y);

    long idx = (long)node * 32 + lane;
    ((float2*)out)[idx] = mu;                                   // mu
    ((float2*)(out + (long)Nn * OUTF))[idx] = mu;               // logstd == mu
    ((float2*)(out + 2L * Nn * OUTF))[idx] = z;                 // zeta
}

extern "C" void kernel_launch(void* const* d_in, const int* in_sizes, int n_in,
                              void* d_out, int out_size) {
    const float* x   = (const float*)d_in[0];
    const void*  ei  = d_in[1];                 // int64 or int32, detected on device
    const float* W1  = (const float*)d_in[2];
    const float* b1  = (const float*)d_in[3];
    const float* Wmu = (const float*)d_in[4];
    const float* bmu = (const float*)d_in[5];
    // d_in[6]=Wls, d_in[7]=bls are dead (reference reuses Wmu/bmu for logstd)
    const float* eps = (const float*)d_in[8];
    float* out = (float*)d_out;

    float *h1p, *hp, *m2p, *dvp;
    cudaGetSymbolAddress((void**)&h1p, g_h1);
    cudaGetSymbolAddress((void**)&hp,  g_h);
    cudaGetSymbolAddress((void**)&m2p, g_m2);
    cudaGetSymbolAddress((void**)&dvp, g_dinv);

    const int TB = 256;
    k_detect<<<1, 32>>>(ei);
    k_zero<<<(Nn + TB - 1) / TB, TB>>>();
    k_deg <<<(Ee + TB - 1) / TB, TB>>>(ei);
    k_scanA<<<SCAN_NB, SCAN_BLK>>>();
    k_scanB<<<1, 32>>>();
    k_scanC<<<SCAN_NB, SCAN_BLK>>>();
    k_fill<<<(Ee + TB - 1) / TB, TB>>>(ei);

    k_gemm<HH><<<(Nn + 63) / 64, 256>>>(x, W1, dvp, h1p, Nn);
    k_agg1<<<(Nn * 32 + TB - 1) / TB, TB>>>(b1);
    k_gemm<OUTF><<<(Nn + 63) / 64, 256>>>(hp, Wmu, dvp, m2p, Nn);
    k_agg2<<<(Nn * 32 + TB - 1) / TB, TB>>>(bmu, eps, out);
}

// round 10
// speedup vs baseline: 1.1839x; 1.0024x over previous
#include <cuda_runtime.h>

#define Nn 50000
#define Ee 800000
#define INF 128
#define HH  128
#define OUTF 64
#define SCAN_BLK 1024
#define SCAN_NB ((Nn + SCAN_BLK - 1) / SCAN_BLK)   // 49

typedef unsigned long long u64;

// ---- packed f32x2 helpers (FFMA2: 2 fp32 FMA per instruction, PTX-only) ----
__device__ __forceinline__ u64 pack2(float lo, float hi) {
    u64 r; asm("mov.b64 %0, {%1, %2};" : "=l"(r) : "f"(lo), "f"(hi)); return r;
}
__device__ __forceinline__ void unpack2(u64 v, float& lo, float& hi) {
    asm("mov.b64 {%0, %1}, %2;" : "=f"(lo), "=f"(hi) : "l"(v));
}
__device__ __forceinline__ u64 ffma2(u64 a, u64 b, u64 c) {
    u64 d; asm("fma.rn.f32x2 %0, %1, %2, %3;" : "=l"(d) : "l"(a), "l"(b), "l"(c)); return d;
}

// ---- device scratch (static globals; no allocation) ----
__device__ __align__(16) float g_h1[Nn * HH];    // (x @ W1) * dinv[row]
__device__ __align__(16) float g_h [Nn * HH];    // relu(conv1) output
__device__ __align__(16) float g_m2[Nn * OUTF];  // (h @ Wmu) * dinv[row]
__device__ int   g_deg [Nn];
__device__ int   g_ptr [Nn + 1];
__device__ int   g_fill[Nn];
__device__ int   g_src [Ee];       // CSR-by-dst neighbor lists
__device__ float g_dinv[Nn];
__device__ int   g_is64;           // 1 if edge_index is int64, 0 if int32
__device__ int   g_bsum[SCAN_NB];  // per-block degree sums
__device__ int   g_boff[SCAN_NB];  // exclusive prefix of block sums

__device__ __forceinline__ int edge_at(const void* ei, int which, int e, int is64) {
    // which: 0 = src row, 1 = dst row, layout [2, E]
    if (is64) return (int)((const long long*)ei)[(long)which * Ee + e];
    return ((const int*)ei)[(long)which * Ee + e];
}

// ---------------- zero + fused dtype detection ----------------
// int64 data: sampled values all in [0, Nn). int32 read as int64 packs two random
// indices per word -> high word nonzero with overwhelming probability.
__global__ void k_zero(const void* ei) {
    int i = blockIdx.x * blockDim.x + threadIdx.x;
    if (i < Nn) { g_deg[i] = 0; g_fill[i] = 0; }
    if (blockIdx.x == 0 && threadIdx.x < 32) {
        int lane = threadIdx.x;
        const long long* p = (const long long*)ei;
        long long v1 = p[lane];            // src row head
        long long v2 = p[Ee + lane];       // dst row head
        bool ok = (v1 >= 0 && v1 < Nn) && (v2 >= 0 && v2 < Nn);
        unsigned all = __all_sync(0xffffffffu, ok);
        if (lane == 0) g_is64 = all ? 1 : 0;
    }
}

__global__ void k_deg(const void* __restrict__ ei) {
    int e = blockIdx.x * blockDim.x + threadIdx.x;
    if (e < Ee) {
        const int is64 = g_is64;
        int d = edge_at(ei, 1, e, is64);
        if (d >= 0 && d < Nn) atomicAdd(&g_deg[d], 1);
    }
}

// ---- 3-phase multi-block scan (dinv fused into phase A) ----
__global__ void k_scanA() {
    __shared__ int warp_sums[32];
    int tid = threadIdx.x, lane = tid & 31, wid = tid >> 5;
    int i = blockIdx.x * SCAN_BLK + tid;
    int v = (i < Nn) ? g_deg[i] : 0;
    if (i < Nn) g_dinv[i] = rsqrtf((float)v + 1.0f);   // fused dinv
    int x = v;
    #pragma unroll
    for (int o = 1; o < 32; o <<= 1) {
        int t = __shfl_up_sync(0xffffffffu, x, o);
        if (lane >= o) x += t;
    }
    if (lane == 31) warp_sums[wid] = x;
    __syncthreads();
    if (wid == 0) {
        int s = warp_sums[lane];
        #pragma unroll
        for (int o = 1; o < 32; o <<= 1) {
            int t = __shfl_up_sync(0xffffffffu, s, o);
            if (lane >= o) s += t;
        }
        warp_sums[lane] = s;
    }
    __syncthreads();
    int incl = x + (wid > 0 ? warp_sums[wid - 1] : 0);
    if (i < Nn) g_ptr[i] = incl - v;                 // block-local exclusive prefix
    if (tid == SCAN_BLK - 1) g_bsum[blockIdx.x] = incl;
}

__global__ void k_scanB() {
    int lane = threadIdx.x;
    int carry = 0;
    for (int base = 0; base < SCAN_NB; base += 32) {
        int idx = base + lane;
        int v = (idx < SCAN_NB) ? g_bsum[idx] : 0;
        int x = v;
        #pragma unroll
        for (int o = 1; o < 32; o <<= 1) {
            int t = __shfl_up_sync(0xffffffffu, x, o);
            if (lane >= o) x += t;
        }
        if (idx < SCAN_NB) g_boff[idx] = carry + x - v;
        carry += __shfl_sync(0xffffffffu, x, 31);
    }
    if (lane == 0) g_ptr[Nn] = Ee;                   // total degree == E (all dst valid)
}

__global__ void k_scanC() {
    int i = blockIdx.x * SCAN_BLK + threadIdx.x;
    if (i < Nn) g_ptr[i] += g_boff[blockIdx.x];
}

__global__ void k_fill(const void* __restrict__ ei) {
    int e = blockIdx.x * blockDim.x + threadIdx.x;
    if (e < Ee) {
        const int is64 = g_is64;
        int d = edge_at(ei, 1, e, is64);
        int s = edge_at(ei, 0, e, is64);
        if (d >= 0 && d < Nn && s >= 0 && s < Nn) {
            int pos = g_ptr[d] + atomicAdd(&g_fill[d], 1);
            if (pos >= 0 && pos < Ee) g_src[pos] = s;
        }
    }
}

// ---- dense GEMM (packed f32x2): Y[row,:] = (X[row,:128] @ W[128,OUTC]) * dscale[row] ----
// block = 256 threads, tile = 64 rows x OUTC cols, K-panels of 32
template <int OUTC>
__global__ void k_gemm(const float* __restrict__ X, const float* __restrict__ W,
                       const float* __restrict__ dscale,
                       float* __restrict__ Y, int nrows) {
    __shared__ float xs[64][33];          // padded to kill bank conflicts
    __shared__ __align__(16) float ws[32 * OUTC];
    constexpr int NH = OUTC / 64;          // 2 for 128, 1 for 64

    int tid  = threadIdx.x;
    int tx   = tid & 15;                   // col group
    int ty   = tid >> 4;                   // row group
    int row0 = blockIdx.x * 64;

    u64 acc2[4][NH * 2];                   // each u64 = 2 packed fp32 accumulators
    #pragma unroll
    for (int i = 0; i < 4; i++)
        #pragma unroll
        for (int j = 0; j < NH * 2; j++) acc2[i][j] = 0ULL;

    int lr = tid >> 2;                     // 0..63 : row for x-tile load
    int lc = (tid & 3) * 8;                // 0,8,16,24 : k-offset for x-tile load

    for (int k0 = 0; k0 < 128; k0 += 32) {
        // load X tile (64 x 32)
        if (row0 + lr < nrows) {
            const float* xp = X + (long)(row0 + lr) * 128 + k0 + lc;
            float4 v0 = *(const float4*)(xp);
            float4 v1 = *(const float4*)(xp + 4);
            xs[lr][lc + 0] = v0.x; xs[lr][lc + 1] = v0.y; xs[lr][lc + 2] = v0.z; xs[lr][lc + 3] = v0.w;
            xs[lr][lc + 4] = v1.x; xs[lr][lc + 5] = v1.y; xs[lr][lc + 6] = v1.z; xs[lr][lc + 7] = v1.w;
        } else {
            #pragma unroll
            for (int j = 0; j < 8; j++) xs[lr][lc + j] = 0.0f;
        }
        // load W panel (32 x OUTC), flat copy
        {
            const float4* wp = (const float4*)(W + k0 * OUTC);
            float4* wsp = (float4*)ws;
            #pragma unroll
            for (int f = 0; f < (32 * OUTC / 4) / 256; f++)
                wsp[tid + f * 256] = wp[tid + f * 256];
        }
        __syncthreads();

        #pragma unroll
        for (int kk = 0; kk < 32; kk++) {
            float a0 = xs[ty * 4 + 0][kk];
            float a1 = xs[ty * 4 + 1][kk];
            float a2 = xs[ty * 4 + 2][kk];
            float a3 = xs[ty * 4 + 3][kk];
            u64 a0p = pack2(a0, a0);
            u64 a1p = pack2(a1, a1);
            u64 a2p = pack2(a2, a2);
            u64 a3p = pack2(a3, a3);
            #pragma unroll
            for (int h2 = 0; h2 < NH; h2++) {
                const u64* wp2 = (const u64*)&ws[kk * OUTC + h2 * 64 + tx * 4];
                u64 w01 = wp2[0];
                u64 w23 = wp2[1];
                acc2[0][h2*2+0] = ffma2(a0p, w01, acc2[0][h2*2+0]);
                acc2[0][h2*2+1] = ffma2(a0p, w23, acc2[0][h2*2+1]);
                acc2[1][h2*2+0] = ffma2(a1p, w01, acc2[1][h2*2+0]);
                acc2[1][h2*2+1] = ffma2(a1p, w23, acc2[1][h2*2+1]);
                acc2[2][h2*2+0] = ffma2(a2p, w01, acc2[2][h2*2+0]);
                acc2[2][h2*2+1] = ffma2(a2p, w23, acc2[2][h2*2+1]);
                acc2[3][h2*2+0] = ffma2(a3p, w01, acc2[3][h2*2+0]);
                acc2[3][h2*2+1] = ffma2(a3p, w23, acc2[3][h2*2+1]);
            }
        }
        __syncthreads();
    }

    #pragma unroll
    for (int i = 0; i < 4; i++) {
        int row = row0 + ty * 4 + i;
        if (row < nrows) {
            float sc = dscale[row];
            #pragma unroll
            for (int h2 = 0; h2 < NH; h2++) {
                float4 v;
                unpack2(acc2[i][h2*2+0], v.x, v.y);
                unpack2(acc2[i][h2*2+1], v.z, v.w);
                v.x *= sc; v.y *= sc; v.z *= sc; v.w *= sc;
                *(float4*)&Y[(long)row * OUTC + h2 * 64 + tx * 4] = v;
            }
        }
    }
}

// ---- aggregation layer 1: warp per dst node ----
// index loads: 1 coalesced LDG per 32 edges + shfl broadcast; row gathers 4-deep.
__global__ void k_agg1(const float* __restrict__ b1) {
    int warp = (blockIdx.x * blockDim.x + threadIdx.x) >> 5;
    int lane = threadIdx.x & 31;
    if (warp >= Nn) return;
    int node = warp;
    int beg = g_ptr[node], end = g_ptr[node + 1];
    float dd = g_dinv[node];
    const float4* __restrict__ H1 = (const float4*)g_h1;

    float4 acc = make_float4(0.f, 0.f, 0.f, 0.f);
    for (int e0 = beg; e0 < end; e0 += 32) {
        int n = end - e0; if (n > 32) n = 32;
        int myidx = (lane < n) ? g_src[e0 + lane] : 0;
        int j = 0;
        for (; j + 4 <= n; j += 4) {
            int s0 = __shfl_sync(0xffffffffu, myidx, j + 0);
            int s1 = __shfl_sync(0xffffffffu, myidx, j + 1);
            int s2 = __shfl_sync(0xffffffffu, myidx, j + 2);
            int s3 = __shfl_sync(0xffffffffu, myidx, j + 3);
            float4 v0 = H1[(long)s0 * 32 + lane];
            float4 v1 = H1[(long)s1 * 32 + lane];
            float4 v2 = H1[(long)s2 * 32 + lane];
            float4 v3 = H1[(long)s3 * 32 + lane];
            acc.x += v0.x + v1.x + v2.x + v3.x;
            acc.y += v0.y + v1.y + v2.y + v3.y;
            acc.z += v0.z + v1.z + v2.z + v3.z;
            acc.w += v0.w + v1.w + v2.w + v3.w;
        }
        for (; j < n; j++) {
            int s = __shfl_sync(0xffffffffu, myidx, j);
            float4 v = H1[(long)s * 32 + lane];
            acc.x += v.x; acc.y += v.y; acc.z += v.z; acc.w += v.w;
        }
    }
    float4 sf = H1[(long)node * 32 + lane];        // self term: already h1*dinv[node]
    float4 b  = ((const float4*)b1)[lane];
    float4 r;
    r.x = fmaxf((acc.x + sf.x) * dd + b.x, 0.f);
    r.y = fmaxf((acc.y + sf.y) * dd + b.y, 0.f);
    r.z = fmaxf((acc.z + sf.z) * dd + b.z, 0.f);
    r.w = fmaxf((acc.w + sf.w) * dd + b.w, 0.f);
    ((float4*)g_h)[(long)node * 32 + lane] = r;
}

// ---- aggregation layer 2 + fused epilogue (mu, logstd=mu, zeta) ----
__global__ void k_agg2(const float* __restrict__ bmu, const float* __restrict__ eps,
                       float* __restrict__ out) {
    int warp = (blockIdx.x * blockDim.x + threadIdx.x) >> 5;
    int lane = threadIdx.x & 31;
    if (warp >= Nn) return;
    int node = warp;
    int beg = g_ptr[node], end = g_ptr[node + 1];
    float dd = g_dinv[node];
    const float2* __restrict__ M = (const float2*)g_m2;

    float2 acc = make_float2(0.f, 0.f);
    for (int e0 = beg; e0 < end; e0 += 32) {
        int n = end - e0; if (n > 32) n = 32;
        int myidx = (lane < n) ? g_src[e0 + lane] : 0;
        int j = 0;
        for (; j + 4 <= n; j += 4) {
            int s0 = __shfl_sync(0xffffffffu, myidx, j + 0);
            int s1 = __shfl_sync(0xffffffffu, myidx, j + 1);
            int s2 = __shfl_sync(0xffffffffu, myidx, j + 2);
            int s3 = __shfl_sync(0xffffffffu, myidx, j + 3);
            float2 v0 = M[(long)s0 * 32 + lane];
            float2 v1 = M[(long)s1 * 32 + lane];
            float2 v2 = M[(long)s2 * 32 + lane];
            float2 v3 = M[(long)s3 * 32 + lane];
            acc.x += v0.x + v1.x + v2.x + v3.x;
            acc.y += v0.y + v1.y + v2.y + v3.y;
        }
        for (; j < n; j++) {
            int s = __shfl_sync(0xffffffffu, myidx, j);
            float2 v = M[(long)s * 32 + lane];
            acc.x += v.x; acc.y += v.y;
        }
    }
    float2 sf = M[(long)node * 32 + lane];
    float2 b  = ((const float2*)bmu)[lane];
    float2 mu;
    mu.x = (acc.x + sf.x) * dd + b.x;
    mu.y = (acc.y + sf.y) * dd + b.y;

    float2 ep = ((const float2*)eps)[(long)node * 32 + lane];
    float2 z;
    z.x = mu.x + ep.x * __expf(mu.x);
    z.y = mu.y + ep.y * __expf(mu.y);

    long idx = (long)node * 32 + lane;
    ((float2*)out)[idx] = mu;                                   // mu
    ((float2*)(out + (long)Nn * OUTF))[idx] = mu;               // logstd == mu
    ((float2*)(out + 2L * Nn * OUTF))[idx] = z;                 // zeta
}

extern "C" void kernel_launch(void* const* d_in, const int* in_sizes, int n_in,
                              void* d_out, int out_size) {
    const float* x   = (const float*)d_in[0];
    const void*  ei  = d_in[1];                 // int64 or int32, detected on device
    const float* W1  = (const float*)d_in[2];
    const float* b1  = (const float*)d_in[3];
    const float* Wmu = (const float*)d_in[4];
    const float* bmu = (const float*)d_in[5];
    // d_in[6]=Wls, d_in[7]=bls are dead (reference reuses Wmu/bmu for logstd)
    const float* eps = (const float*)d_in[8];
    float* out = (float*)d_out;

    float *h1p, *hp, *m2p, *dvp;
    cudaGetSymbolAddress((void**)&h1p, g_h1);
    cudaGetSymbolAddress((void**)&hp,  g_h);
    cudaGetSymbolAddress((void**)&m2p, g_m2);
    cudaGetSymbolAddress((void**)&dvp, g_dinv);

    const int TB = 256;
    k_zero<<<(Nn + TB - 1) / TB, TB>>>(ei);     // zero + fused dtype detection
    k_deg <<<(Ee + TB - 1) / TB, TB>>>(ei);
    k_scanA<<<SCAN_NB, SCAN_BLK>>>();
    k_scanB<<<1, 32>>>();
    k_scanC<<<SCAN_NB, SCAN_BLK>>>();
    k_fill<<<(Ee + TB - 1) / TB, TB>>>(ei);

    k_gemm<HH><<<(Nn + 63) / 64, 256>>>(x, W1, dvp, h1p, Nn);
    k_agg1<<<(Nn * 32 + TB - 1) / TB, TB>>>(b1);
    k_gemm<OUTF><<<(Nn + 63) / 64, 256>>>(hp, Wmu, dvp, m2p, Nn);
    k_agg2<<<(Nn * 32 + TB - 1) / TB, TB>>>(bmu, eps, out);
}